// round 17
// baseline (speedup 1.0000x reference)
#include <cuda_runtime.h>
#include <cuda_fp16.h>
#include <cstdint>
#include <math.h>

// Problem constants (fixed shapes)
#define B_   2
#define T_   2048
#define D_   2048
#define H_   16
#define HD_  128
#define M_   (B_ * T_)      // 4096 rows
#define N1_  (3 * D_)       // 6144 qkv cols
#define SCALE_ 0.022097086912079612f   // 2048^-0.5  (D, not head_dim!)

// ---------------------------------------------------------------------------
// Scratch (device globals — no allocation allowed)
// ---------------------------------------------------------------------------
__device__ __half g_x16[(size_t)M_ * D_];
__device__ __half g_wq16[(size_t)N1_ * D_];
__device__ __half g_attn16[(size_t)M_ * D_];
__device__ __half g_wo16[(size_t)D_ * D_];
#define QKV_ELEMS ((size_t)B_ * H_ * T_ * HD_)
__device__ __half g_q16[QKV_ELEMS];
__device__ __half g_k16[QKV_ELEMS];
__device__ __half g_v16[QKV_ELEMS];

// ---------------------------------------------------------------------------
// PTX helpers (family-portable: ldmatrix / mma.sync / cp.async)
// ---------------------------------------------------------------------------
__device__ __forceinline__ uint32_t smem_to_u32(const void* p) {
    uint32_t a;
    asm("{ .reg .u64 t; cvta.to.shared.u64 t, %1; cvt.u32.u64 %0, t; }"
        : "=r"(a) : "l"(p));
    return a;
}
#define SMEM_SWIZZLE_128B(off) ((off) ^ (((off) >> 3) & 0x70))

#define CP_ASYNC16(dst, src) \
    asm volatile("cp.async.cg.shared.global [%0], [%1], 16;" \
                 :: "r"((uint32_t)(dst)), "l"(src))
#define CP_ASYNC_COMMIT() asm volatile("cp.async.commit_group;" ::: "memory")

__device__ __forceinline__ void ldsm4(uint32_t* r, uint32_t addr) {
    asm volatile("ldmatrix.sync.aligned.m8n8.x4.shared.b16 {%0,%1,%2,%3}, [%4];"
                 : "=r"(r[0]), "=r"(r[1]), "=r"(r[2]), "=r"(r[3]) : "r"(addr));
}
__device__ __forceinline__ void ldsm4t(uint32_t* r, uint32_t addr) {
    asm volatile("ldmatrix.sync.aligned.m8n8.x4.trans.shared.b16 {%0,%1,%2,%3}, [%4];"
                 : "=r"(r[0]), "=r"(r[1]), "=r"(r[2]), "=r"(r[3]) : "r"(addr));
}

__device__ __forceinline__ void mma16816f(float* c, const uint32_t* a,
                                          uint32_t b0, uint32_t b1) {
    asm volatile(
        "mma.sync.aligned.m16n8k16.row.col.f32.f16.f16.f32 "
        "{%0,%1,%2,%3}, {%4,%5,%6,%7}, {%8,%9}, {%0,%1,%2,%3};"
        : "+f"(c[0]), "+f"(c[1]), "+f"(c[2]), "+f"(c[3])
        : "r"(a[0]), "r"(a[1]), "r"(a[2]), "r"(a[3]), "r"(b0), "r"(b1));
}

__device__ __forceinline__ uint32_t pack2h(float p0, float p1) {
    __half2 hh = __floats2half2_rn(p0, p1);
    return *(uint32_t*)&hh;
}

// ---------------------------------------------------------------------------
// fp32 -> fp16 convert, vectorized
// ---------------------------------------------------------------------------
__global__ __launch_bounds__(256) void conv_fp16(
    const float* __restrict__ src, __half* __restrict__ dst)
{
    const int i = blockIdx.x * 256 + threadIdx.x;   // float4 index
    float4 v = ((const float4*)src)[i];
    __half2 a = __floats2half2_rn(v.x, v.y);
    __half2 b = __floats2half2_rn(v.z, v.w);
    ((uint2*)dst)[i] = make_uint2(*(uint32_t*)&a, *(uint32_t*)&b);
}

// ---------------------------------------------------------------------------
// Shared GEMM machinery: CTA 128x128, BK=64, 8 warps (2m x 4n),
// 1 fp16 MMA per (mt,nt) per k16. 2 x 32KB smem buffers, SW128, 128B rows.
// ---------------------------------------------------------------------------
#define G_SMEM_BYTES (2 * 32768 + 1024)

__device__ __forceinline__ void load_chunk2(
    const __half* A, const __half* Bw,
    int bm, int bn, int K, int k0, uint32_t dbase, int tid)
{
#pragma unroll
    for (int i = 0; i < 8; i++) {
        const int idx = tid + i * 256;
        const int t   = idx >> 10;           // 0:A 1:B
        const int r   = (idx >> 3) & 127;
        const int c16 = idx & 7;
        const __half* sp = t ? Bw : A;
        const int row = (t ? bn : bm) + r;
        const char* src = (const char*)sp +
            (((size_t)row * K + k0) << 1) + (c16 << 4);
        const uint32_t off = (r << 7) + (c16 << 4);
        const uint32_t dst = dbase + (t << 14) + SMEM_SWIZZLE_128B(off);
        CP_ASYNC16(dst, src);
    }
    CP_ASYNC_COMMIT();
}

// Mainloop body shared by both GEMM kernels (accumulates into acc).
#define GEMM_MAINLOOP(A16, Bw, bm, bn, K)                                      \
    const int nchunks = (K) >> 6;                                              \
    load_chunk2(A16, Bw, bm, bn, K, 0, data0, tid);                            \
    for (int c = 0; c < nchunks; c++) {                                        \
        if (c + 1 < nchunks) {                                                 \
            load_chunk2(A16, Bw, bm, bn, K, (c + 1) << 6,                      \
                        data0 + ((c + 1) & 1) * 32768, tid);                   \
            asm volatile("cp.async.wait_group 1;" ::: "memory");               \
        } else {                                                               \
            asm volatile("cp.async.wait_group 0;" ::: "memory");               \
        }                                                                      \
        __syncthreads();                                                       \
        const uint32_t dbase = data0 + (c & 1) * 32768;                        \
        const uint32_t sA = dbase;                                             \
        const uint32_t sB = dbase + 16384;                                     \
        _Pragma("unroll")                                                      \
        for (int ks = 0; ks < 4; ks++) {                                       \
            const uint32_t kbyte = (uint32_t)ks << 5;                          \
            uint32_t af_[4][4];                                                \
            _Pragma("unroll")                                                  \
            for (int mt = 0; mt < 4; mt++) {                                   \
                const uint32_t off = ((a_row + mt * 16) << 7) + kbyte + a_kb;  \
                ldsm4(af_[mt], sA + SMEM_SWIZZLE_128B(off));                   \
            }                                                                  \
            uint32_t bf_[2][4];                                                \
            _Pragma("unroll")                                                  \
            for (int ng = 0; ng < 2; ng++) {                                   \
                const uint32_t off = ((b_row + ng * 16) << 7) + kbyte + b_kb;  \
                ldsm4(bf_[ng], sB + SMEM_SWIZZLE_128B(off));                   \
            }                                                                  \
            _Pragma("unroll")                                                  \
            for (int mt = 0; mt < 4; mt++) {                                   \
                _Pragma("unroll")                                              \
                for (int nt = 0; nt < 4; nt++) {                               \
                    const int ng = nt >> 1, lo = (nt & 1) * 2;                 \
                    mma16816f(acc[mt][nt], af_[mt], bf_[ng][lo],               \
                              bf_[ng][lo + 1]);                                \
                }                                                              \
            }                                                                  \
        }                                                                      \
        __syncthreads();                                                       \
    }

// ---------------------------------------------------------------------------
// GEMM2: out(fp32) = attn16 @ wo16^T + b_out   (R16 passing version)
// ---------------------------------------------------------------------------
__global__ __launch_bounds__(256, 1) void gemm_ssf(
    const __half* __restrict__ A16, const __half* __restrict__ Bw,
    const float* __restrict__ bias, float* __restrict__ C,
    int M, int N, int K)
{
    extern __shared__ __align__(16) char smem[];
    const uint32_t data0 = (smem_to_u32(smem) + 1023) & ~1023u;

    const int tid  = threadIdx.x;
    const int lane = tid & 31;
    const int wid  = tid >> 5;
    const int warp_m = wid >> 2;
    const int warp_n = wid & 3;
    const int bm = blockIdx.y * 128;
    const int bn = blockIdx.x * 128;

    const uint32_t a_row = warp_m * 64 + (lane & 15);
    const uint32_t a_kb  = (uint32_t)(lane >> 4) << 4;
    const uint32_t b_row = warp_n * 32 + (lane & 7) + (((uint32_t)lane >> 4) << 3);
    const uint32_t b_kb  = (((uint32_t)lane >> 3) & 1) << 4;

    float acc[4][4][4];
#pragma unroll
    for (int mt = 0; mt < 4; mt++)
#pragma unroll
        for (int nt = 0; nt < 4; nt++)
#pragma unroll
            for (int r = 0; r < 4; r++) acc[mt][nt][r] = 0.0f;

    GEMM_MAINLOOP(A16, Bw, bm, bn, K)

    const int gm0 = bm + warp_m * 64 + (lane >> 2);
    const int gn0 = bn + warp_n * 32 + (lane & 3) * 2;
#pragma unroll
    for (int mt = 0; mt < 4; mt++) {
#pragma unroll
        for (int nt = 0; nt < 4; nt++) {
            const int gm = gm0 + mt * 16;
            const int gn = gn0 + nt * 8;
            const float b0 = bias[gn], b1 = bias[gn + 1];
            *(float2*)&C[(size_t)gm * N + gn] =
                make_float2(acc[mt][nt][0] + b0, acc[mt][nt][1] + b1);
            *(float2*)&C[(size_t)(gm + 8) * N + gn] =
                make_float2(acc[mt][nt][2] + b0, acc[mt][nt][3] + b1);
        }
    }
}

// ---------------------------------------------------------------------------
// GEMM1 with FUSED RoPE + head-split epilogue.
// N-tile alignment: 384 cols/head = 3 x 128 ==> blockIdx.x % 3 selects q/k/v,
// blockIdx.x / 3 selects head. Tile staged as fp16 in smem (mainloop buffers
// are free after the last sync), then:
//   v-tile: straight copy to g_v16 [bh][t][hd]
//   q/k-tile: rope rotation (same powf/cosf/sinf numerics as the retired
//             rope kernel; fp16 staging == the old fp16 qkv roundtrip)
// ---------------------------------------------------------------------------
#define ST_STRIDE 272   // bytes per staged row (128 halfs + pad)

__global__ __launch_bounds__(256, 1) void gemm_qkv(
    const __half* __restrict__ A16, const __half* __restrict__ Bw,
    const float* __restrict__ bias,
    __half* __restrict__ Q16, __half* __restrict__ K16h,
    __half* __restrict__ V16,
    int M, int N, int K)
{
    extern __shared__ __align__(16) char smem[];
    const uint32_t sbase = smem_to_u32(smem);
    const uint32_t data0 = (sbase + 1023) & ~1023u;
    char* sm_c = smem + (data0 - sbase);     // C-pointer to data0 region

    const int tid  = threadIdx.x;
    const int lane = tid & 31;
    const int wid  = tid >> 5;
    const int warp_m = wid >> 2;
    const int warp_n = wid & 3;
    const int bm = blockIdx.y * 128;
    const int bn = blockIdx.x * 128;

    const uint32_t a_row = warp_m * 64 + (lane & 15);
    const uint32_t a_kb  = (uint32_t)(lane >> 4) << 4;
    const uint32_t b_row = warp_n * 32 + (lane & 7) + (((uint32_t)lane >> 4) << 3);
    const uint32_t b_kb  = (((uint32_t)lane >> 3) & 1) << 4;

    float acc[4][4][4];
#pragma unroll
    for (int mt = 0; mt < 4; mt++)
#pragma unroll
        for (int nt = 0; nt < 4; nt++)
#pragma unroll
            for (int r = 0; r < 4; r++) acc[mt][nt][r] = 0.0f;

    GEMM_MAINLOOP(A16, Bw, bm, bn, K)

    // ---- stage tile (+bias) as fp16 into smem ----
    {
        const int r0l = warp_m * 64 + (lane >> 2);
        const int c0l = warp_n * 32 + (lane & 3) * 2;
#pragma unroll
        for (int mt = 0; mt < 4; mt++) {
#pragma unroll
            for (int nt = 0; nt < 4; nt++) {
                const int r = r0l + mt * 16;
                const int cc = c0l + nt * 8;
                const float b0 = bias[bn + cc], b1 = bias[bn + cc + 1];
                *(uint32_t*)(sm_c + r * ST_STRIDE + cc * 2) =
                    pack2h(acc[mt][nt][0] + b0, acc[mt][nt][1] + b1);
                *(uint32_t*)(sm_c + (r + 8) * ST_STRIDE + cc * 2) =
                    pack2h(acc[mt][nt][2] + b0, acc[mt][nt][3] + b1);
            }
        }
    }
    __syncthreads();

    // ---- fused rope / split epilogue ----
    const int type = blockIdx.x % 3;        // 0:q 1:k 2:v
    const int head = blockIdx.x / 3;
    const int bq   = bm >> 11;              // batch (tile never straddles)
    const int t0   = bm & (T_ - 1);
    const size_t gb = ((size_t)(bq * H_ + head) * T_) * HD_;

    if (type == 2) {
        // plain convert-copy to v16 [bh][t][hd]
        const int r  = tid >> 1;
        const int hf = tid & 1;
        const char* srow = sm_c + r * ST_STRIDE + hf * 128;
        char* grow = (char*)(V16 + gb + (size_t)(t0 + r) * HD_) + hf * 128;
#pragma unroll
        for (int j = 0; j < 8; j++)
            *(uint4*)(grow + j * 16) = *(const uint4*)(srow + j * 16);
    } else {
        __half* dst = (type == 0) ? Q16 : K16h;
        const int r  = tid >> 1;
        const int i0 = (tid & 1) * 32;      // this thread: i in [i0, i0+32)
        const int t  = t0 + r;
        const __half* srow = (const __half*)(sm_c + r * ST_STRIDE);
        __half outb[64];                    // cols [i0,i0+32) and [i0+64,+32)
#pragma unroll 4
        for (int ii = 0; ii < 32; ii++) {
            const int i = i0 + ii;
            const float a1 = __half2float(srow[i]);
            const float a2 = __half2float(srow[i + 64]);
            const float theta = powf(10000.0f, -(float)i * (1.0f / 64.0f));
            const float ang = (float)t * theta;
            const float cs = cosf(ang), sn = sinf(ang);
            outb[ii]      = __float2half(a1 * cs - a2 * sn);
            outb[32 + ii] = __float2half(a1 * sn + a2 * cs);
        }
        char* grow = (char*)(dst + gb + (size_t)t * HD_);
#pragma unroll
        for (int j = 0; j < 4; j++)
            *(uint4*)(grow + i0 * 2 + j * 16) = ((uint4*)outb)[j];
#pragma unroll
        for (int j = 0; j < 4; j++)
            *(uint4*)(grow + 128 + i0 * 2 + j * 16) = ((uint4*)(outb + 32))[j];
    }
}

// ---------------------------------------------------------------------------
// Causal flash attention, single fp16 Q/K/V/P, fp32 accum + softmax.
// (unchanged from R16 passing version)
// ---------------------------------------------------------------------------
#define FL_SMEM_BYTES 104448
#define FL_STRIDE 272

__device__ __forceinline__ void fl_load_kv16(
    const __half* K16, const __half* V16,
    size_t goff, uint32_t sbuf, int tid)
{
#pragma unroll
    for (int i = 0; i < 8; i++) {
        const int idx = tid + i * 256;
        const int arr = idx >> 10;          // 0:K 1:V
        const int r   = (idx >> 4) & 63;
        const int seg = idx & 15;
        const __half* p = arr ? V16 : K16;
        const char* src = (const char*)p + ((goff + (size_t)r * HD_) << 1) + (seg << 4);
        const uint32_t dst = sbuf + arr * 17408 + r * FL_STRIDE + (seg << 4);
        CP_ASYNC16(dst, src);
    }
    CP_ASYNC_COMMIT();
}

__global__ __launch_bounds__(256, 1) void flash_hmma16(
    const __half* __restrict__ Q16, const __half* __restrict__ K16,
    const __half* __restrict__ V16, __half* __restrict__ O16)
{
    extern __shared__ __align__(16) char smc[];
    const uint32_t sb  = smem_to_u32(smc);
    const uint32_t sQ  = sb;
    const uint32_t sKV = sb + 34816;            // + buf*34816

    const int tid  = threadIdx.x;
    const int lane = tid & 31;
    const int warp = tid >> 5;
    const int qt = 15 - (int)blockIdx.x;        // heavy blocks first
    const int bh = blockIdx.y;
    const int b = bh >> 4, h = bh & 15;
    const size_t gbase = (size_t)bh * T_ * HD_;

    // Q load
    {
        const size_t qoff = gbase + (size_t)qt * 128 * HD_;
#pragma unroll
        for (int i = 0; i < 8; i++) {
            const int idx = tid + i * 256;
            const int r   = (idx >> 4) & 127;
            const int seg = idx & 15;
            const char* src = (const char*)Q16 +
                ((qoff + (size_t)r * HD_) << 1) + (seg << 4);
            CP_ASYNC16(sQ + r * FL_STRIDE + (seg << 4), src);
        }
        CP_ASYNC_COMMIT();
    }
    fl_load_kv16(K16, V16, gbase, sKV, tid);

    const int r0w = warp * 16;
    const uint32_t aoff = (r0w + (lane & 15)) * FL_STRIDE + ((lane >> 4) << 4);
    const uint32_t boff = ((lane & 7) + ((lane >> 4) << 3)) * FL_STRIDE +
                          (((lane >> 3) & 1) << 4);
    const uint32_t vrow = (lane & 7) + (((lane >> 3) & 1) << 3);
    const uint32_t vcol = (lane >> 4) << 4;

    float o[16][4];
#pragma unroll
    for (int nt = 0; nt < 16; nt++)
#pragma unroll
        for (int r = 0; r < 4; r++) o[nt][r] = 0.0f;
    float m_[2] = {-1e30f, -1e30f};
    float l_[2] = {0.0f, 0.0f};

    const int ktmax = 2 * qt + 1;
    for (int kt = 0; kt <= ktmax; kt++) {
        if (kt > 0) __syncthreads();
        if (kt < ktmax) {
            fl_load_kv16(K16, V16, gbase + (size_t)(kt + 1) * 64 * HD_,
                         sKV + ((kt + 1) & 1) * 34816, tid);
            asm volatile("cp.async.wait_group 1;" ::: "memory");
        } else {
            asm volatile("cp.async.wait_group 0;" ::: "memory");
        }
        __syncthreads();

        const uint32_t kb = sKV + (kt & 1) * 34816;
        const uint32_t sK = kb, sV = kb + 17408;

        // ---- S = Q K^T (single fp16) ----
        float s[8][4];
#pragma unroll
        for (int nt = 0; nt < 8; nt++)
#pragma unroll
            for (int r = 0; r < 4; r++) s[nt][r] = 0.0f;

#pragma unroll
        for (int ks = 0; ks < 8; ks++) {
            const uint32_t kbyte = (uint32_t)ks << 5;
            uint32_t aq[4];
            ldsm4(aq, sQ + aoff + kbyte);
            uint32_t bk[4][4];
#pragma unroll
            for (int np = 0; np < 4; np++)
                ldsm4(bk[np], sK + boff + np * 16 * FL_STRIDE + kbyte);
#pragma unroll
            for (int nt = 0; nt < 8; nt++) {
                const int ng = nt >> 1, lo = (nt & 1) * 2;
                mma16816f(s[nt], aq, bk[ng][lo], bk[ng][lo + 1]);
            }
        }

        // ---- scale + mask + online softmax (fp32) ----
        const int qa = qt * 128 + r0w + (lane >> 2);
        const int qb = qa + 8;
        const bool dg = (kt >= 2 * qt);
#pragma unroll
        for (int nt = 0; nt < 8; nt++) {
            const int c0 = kt * 64 + nt * 8 + (lane & 3) * 2;
            s[nt][0] *= SCALE_; s[nt][1] *= SCALE_;
            s[nt][2] *= SCALE_; s[nt][3] *= SCALE_;
            if (dg) {
                if (c0     > qa) s[nt][0] = -1e30f;
                if (c0 + 1 > qa) s[nt][1] = -1e30f;
                if (c0     > qb) s[nt][2] = -1e30f;
                if (c0 + 1 > qb) s[nt][3] = -1e30f;
            }
        }
        float ma = -1e30f, mb = -1e30f;
#pragma unroll
        for (int nt = 0; nt < 8; nt++) {
            ma = fmaxf(ma, fmaxf(s[nt][0], s[nt][1]));
            mb = fmaxf(mb, fmaxf(s[nt][2], s[nt][3]));
        }
        ma = fmaxf(ma, __shfl_xor_sync(0xFFFFFFFF, ma, 1));
        ma = fmaxf(ma, __shfl_xor_sync(0xFFFFFFFF, ma, 2));
        mb = fmaxf(mb, __shfl_xor_sync(0xFFFFFFFF, mb, 1));
        mb = fmaxf(mb, __shfl_xor_sync(0xFFFFFFFF, mb, 2));
        const float mna = fmaxf(m_[0], ma), mnb = fmaxf(m_[1], mb);
        const float ca = __expf(m_[0] - mna), cb = __expf(m_[1] - mnb);
        float suma = 0.0f, sumb = 0.0f;
#pragma unroll
        for (int nt = 0; nt < 8; nt++) {
            s[nt][0] = __expf(s[nt][0] - mna); suma += s[nt][0];
            s[nt][1] = __expf(s[nt][1] - mna); suma += s[nt][1];
            s[nt][2] = __expf(s[nt][2] - mnb); sumb += s[nt][2];
            s[nt][3] = __expf(s[nt][3] - mnb); sumb += s[nt][3];
        }
        suma += __shfl_xor_sync(0xFFFFFFFF, suma, 1);
        suma += __shfl_xor_sync(0xFFFFFFFF, suma, 2);
        sumb += __shfl_xor_sync(0xFFFFFFFF, sumb, 1);
        sumb += __shfl_xor_sync(0xFFFFFFFF, sumb, 2);
        l_[0] = l_[0] * ca + suma;  m_[0] = mna;
        l_[1] = l_[1] * cb + sumb;  m_[1] = mnb;
#pragma unroll
        for (int nt = 0; nt < 16; nt++) {
            o[nt][0] *= ca; o[nt][1] *= ca;
            o[nt][2] *= cb; o[nt][3] *= cb;
        }

        // ---- P fragments (single fp16) ----
        uint32_t pa[4][4];
#pragma unroll
        for (int j = 0; j < 4; j++) {
            pa[j][0] = pack2h(s[2 * j][0],     s[2 * j][1]);
            pa[j][1] = pack2h(s[2 * j][2],     s[2 * j][3]);
            pa[j][2] = pack2h(s[2 * j + 1][0], s[2 * j + 1][1]);
            pa[j][3] = pack2h(s[2 * j + 1][2], s[2 * j + 1][3]);
        }

        // ---- O += P V (single fp16), V via ldmatrix.trans ----
#pragma unroll
        for (int j = 0; j < 4; j++) {
            const uint32_t rbase = (j * 16 + vrow) * FL_STRIDE + vcol;
#pragma unroll
            for (int dp = 0; dp < 8; dp++) {
                uint32_t vv[4];
                ldsm4t(vv, sV + rbase + dp * 32);
                mma16816f(o[dp * 2],     pa[j], vv[0], vv[1]);
                mma16816f(o[dp * 2 + 1], pa[j], vv[2], vv[3]);
            }
        }
    }

    // ---- epilogue: normalize, write single fp16 to [B*T][D] ----
    const float inva = 1.0f / l_[0], invb = 1.0f / l_[1];
    const int ta = qt * 128 + r0w + (lane >> 2);
    const size_t rowa = (size_t)(b * T_ + ta) * D_;
    const size_t rowb = rowa + 8 * D_;
    const int cb0 = h * HD_ + (lane & 3) * 2;
#pragma unroll
    for (int nt = 0; nt < 16; nt++) {
        *(uint32_t*)(O16 + rowa + cb0 + nt * 8) =
            pack2h(o[nt][0] * inva, o[nt][1] * inva);
        *(uint32_t*)(O16 + rowb + cb0 + nt * 8) =
            pack2h(o[nt][2] * invb, o[nt][3] * invb);
    }
}

// ---------------------------------------------------------------------------
// kernel_launch
// ---------------------------------------------------------------------------
extern "C" void kernel_launch(void* const* d_in, const int* in_sizes, int n_in,
                              void* d_out, int out_size)
{
    const float* x     = (const float*)d_in[0];
    const float* w_qkv = (const float*)d_in[1];
    const float* b_qkv = (const float*)d_in[2];
    const float* w_out = (const float*)d_in[3];
    const float* b_out = (const float*)d_in[4];
    float* out = (float*)d_out;

    __half *x16, *wq16, *attn16, *wo16, *q16, *k16, *v16;
    cudaGetSymbolAddress((void**)&x16,    g_x16);
    cudaGetSymbolAddress((void**)&wq16,   g_wq16);
    cudaGetSymbolAddress((void**)&attn16, g_attn16);
    cudaGetSymbolAddress((void**)&wo16,   g_wo16);
    cudaGetSymbolAddress((void**)&q16,    g_q16);
    cudaGetSymbolAddress((void**)&k16,    g_k16);
    cudaGetSymbolAddress((void**)&v16,    g_v16);

    cudaFuncSetAttribute(gemm_qkv,
                         cudaFuncAttributeMaxDynamicSharedMemorySize,
                         G_SMEM_BYTES);
    cudaFuncSetAttribute(gemm_ssf,
                         cudaFuncAttributeMaxDynamicSharedMemorySize,
                         G_SMEM_BYTES);
    cudaFuncSetAttribute(flash_hmma16,
                         cudaFuncAttributeMaxDynamicSharedMemorySize,
                         FL_SMEM_BYTES);

    // 0) x, w_qkv -> fp16
    conv_fp16<<<((size_t)M_ * D_) / 1024, 256>>>(x, x16);
    conv_fp16<<<((size_t)N1_ * D_) / 1024, 256>>>(w_qkv, wq16);
    // 1) qkv GEMM with fused RoPE + head split -> q16/k16/v16 directly
    gemm_qkv<<<dim3(N1_ / 128, M_ / 128), 256, G_SMEM_BYTES>>>(
        x16, wq16, b_qkv, q16, k16, v16, M_, N1_, D_);
    // 2) causal flash attention (single fp16) -> attn fp16
    flash_hmma16<<<dim3(16, B_ * H_), 256, FL_SMEM_BYTES>>>(
        q16, k16, v16, attn16);
    // 3) w_out -> fp16 ; out = attn16 @ wo16^T + b_out
    conv_fp16<<<((size_t)D_ * D_) / 1024, 256>>>(w_out, wo16);
    gemm_ssf<<<dim3(D_ / 128, M_ / 128), 256, G_SMEM_BYTES>>>(
        attn16, wo16, b_out, out, M_, D_, D_);
}